// round 4
// baseline (speedup 1.0000x reference)
#include <cuda_runtime.h>
#include <cstdint>
#include <math.h>

// Problem constants
constexpr int NB = 4;      // batch
constexpr int NT = 2048;   // seq len
constexpr int NK = 1024;   // model dim
constexpr int NH = 16;     // heads
constexpr int ND = 64;     // head dim
constexpr int MROWS = NB * NT;  // 8192

// Scratch (allocation-free rule: __device__ globals)
__device__ float g_q[NB * NH * NT * ND];    // [B,H,T,HD], pre-scaled
__device__ float g_k[NB * NH * NT * ND];    // [B,H,T,HD], pre-scaled
__device__ float g_v[NB * NH * NT * ND];    // [B,H,T,HD]
__device__ float g_ctx[MROWS * NK];         // [B*T, K] attention output

// ---------------------------------------------------------------------------
// tf32 helpers
// ---------------------------------------------------------------------------
__device__ __forceinline__ uint32_t f2tf(float f) {
    uint32_t u;
    asm("cvt.rna.tf32.f32 %0, %1;" : "=r"(u) : "f"(f));
    return u;
}

__device__ __forceinline__ void mma_tf32(float* c, const uint32_t* a, const uint32_t* b) {
    asm volatile(
        "mma.sync.aligned.m16n8k8.row.col.f32.tf32.tf32.f32 "
        "{%0,%1,%2,%3}, {%4,%5,%6,%7}, {%8,%9}, {%0,%1,%2,%3};"
        : "+f"(c[0]), "+f"(c[1]), "+f"(c[2]), "+f"(c[3])
        : "r"(a[0]), "r"(a[1]), "r"(a[2]), "r"(a[3]), "r"(b[0]), "r"(b[1]));
}

// ---------------------------------------------------------------------------
// tf32 GEMM: C = A(MxK) @ W^T (W is [N,K] row-major)
// Block 128x128, BK=32, double-buffered smem with register-staged prefetch.
// 8 warps (2x4), each warp 64x32.
// mode 0: scatter to [B,H,T,HD], multiply by scale
// mode 1: write [M,N] row-major + bias[n]
// ---------------------------------------------------------------------------
constexpr int GST = 36;                     // smem row stride (BK=32 + 4 pad)
constexpr int GTILE = 128 * GST;            // u32 per tile-buffer
constexpr int GEMM_SMEM_BYTES = 4 * GTILE * 4;  // As0,As1,Ws0,Ws1

__global__ __launch_bounds__(256)
void gemm_tf32(const float* __restrict__ A, const float* __restrict__ W,
               const float* __restrict__ bias, float* __restrict__ C,
               float scale, int mode)
{
    extern __shared__ uint32_t sg[];
    uint32_t* Asb[2] = { sg,             sg + GTILE     };
    uint32_t* Wsb[2] = { sg + 2 * GTILE, sg + 3 * GTILE };

    const int tid = threadIdx.x;
    const int warp = tid >> 5, lane = tid & 31;
    const int g = lane >> 2, i4 = lane & 3;
    const int mw = warp >> 2;   // 0..1 -> 64-row slab
    const int nw = warp & 3;    // 0..3 -> 32-col slab
    const int row0 = blockIdx.y * 128;
    const int col0 = blockIdx.x * 128;

    const int lr = tid >> 1;           // 0..127 (load row)
    const int lc = (tid & 1) * 16;     // 0 or 16 (load col base)

    const float* pa = &A[(size_t)(row0 + lr) * NK + lc];
    const float* pw = &W[(size_t)(col0 + lr) * NK + lc];

    float4 ra0, ra1, ra2, ra3, rw0, rw1, rw2, rw3;

    auto prefetch = [&](int k0) {
        ra0 = *(const float4*)(pa + k0);     ra1 = *(const float4*)(pa + k0 + 4);
        ra2 = *(const float4*)(pa + k0 + 8); ra3 = *(const float4*)(pa + k0 + 12);
        rw0 = *(const float4*)(pw + k0);     rw1 = *(const float4*)(pw + k0 + 4);
        rw2 = *(const float4*)(pw + k0 + 8); rw3 = *(const float4*)(pw + k0 + 12);
    };
    auto store_stage = [&](int buf) {
        uint32_t* d = &Asb[buf][lr * GST + lc];
        d[0]=f2tf(ra0.x); d[1]=f2tf(ra0.y); d[2]=f2tf(ra0.z); d[3]=f2tf(ra0.w);
        d[4]=f2tf(ra1.x); d[5]=f2tf(ra1.y); d[6]=f2tf(ra1.z); d[7]=f2tf(ra1.w);
        d[8]=f2tf(ra2.x); d[9]=f2tf(ra2.y); d[10]=f2tf(ra2.z); d[11]=f2tf(ra2.w);
        d[12]=f2tf(ra3.x); d[13]=f2tf(ra3.y); d[14]=f2tf(ra3.z); d[15]=f2tf(ra3.w);
        uint32_t* e = &Wsb[buf][lr * GST + lc];
        e[0]=f2tf(rw0.x); e[1]=f2tf(rw0.y); e[2]=f2tf(rw0.z); e[3]=f2tf(rw0.w);
        e[4]=f2tf(rw1.x); e[5]=f2tf(rw1.y); e[6]=f2tf(rw1.z); e[7]=f2tf(rw1.w);
        e[8]=f2tf(rw2.x); e[9]=f2tf(rw2.y); e[10]=f2tf(rw2.z); e[11]=f2tf(rw2.w);
        e[12]=f2tf(rw3.x); e[13]=f2tf(rw3.y); e[14]=f2tf(rw3.z); e[15]=f2tf(rw3.w);
    };

    float acc[4][4][4] = {};  // [mfrag][nfrag][4]

    prefetch(0);
    store_stage(0);
    __syncthreads();

    constexpr int ITERS = NK / 32;   // 32
    for (int it = 0; it < ITERS; it++) {
        const int cur = it & 1;
        if (it + 1 < ITERS) prefetch((it + 1) * 32);

        const uint32_t* As = Asb[cur];
        const uint32_t* Ws = Wsb[cur];
        #pragma unroll
        for (int kk = 0; kk < 32; kk += 8) {
            uint32_t af[4][4], bf[4][2];
            #pragma unroll
            for (int mf = 0; mf < 4; mf++) {
                int mr = mw * 64 + mf * 16;
                af[mf][0] = As[(mr + g    ) * GST + kk + i4];
                af[mf][1] = As[(mr + g + 8) * GST + kk + i4];
                af[mf][2] = As[(mr + g    ) * GST + kk + i4 + 4];
                af[mf][3] = As[(mr + g + 8) * GST + kk + i4 + 4];
            }
            #pragma unroll
            for (int nf = 0; nf < 4; nf++) {
                int nc = nw * 32 + nf * 8;
                bf[nf][0] = Ws[(nc + g) * GST + kk + i4];
                bf[nf][1] = Ws[(nc + g) * GST + kk + i4 + 4];
            }
            #pragma unroll
            for (int mf = 0; mf < 4; mf++)
                #pragma unroll
                for (int nf = 0; nf < 4; nf++)
                    mma_tf32(acc[mf][nf], af[mf], bf[nf]);
        }
        if (it + 1 < ITERS) store_stage(cur ^ 1);
        __syncthreads();
    }

    // epilogue
    #pragma unroll
    for (int mf = 0; mf < 4; mf++) {
        int r_lo = row0 + mw * 64 + mf * 16 + g;
        int r_hi = r_lo + 8;
        #pragma unroll
        for (int nf = 0; nf < 4; nf++) {
            int c0c = col0 + nw * 32 + nf * 8 + 2 * i4;
            if (mode == 0) {
                #pragma unroll
                for (int e = 0; e < 4; e++) {
                    int m = (e >= 2) ? r_hi : r_lo;
                    int n = c0c + (e & 1);
                    int bb = m >> 11, t = m & (NT - 1);   // NT=2048
                    int h = n >> 6, d = n & 63;
                    C[(((size_t)bb * NH + h) * NT + t) * ND + d] = acc[mf][nf][e] * scale;
                }
            } else {
                *(float2*)&C[(size_t)r_lo * NK + c0c] =
                    make_float2(acc[mf][nf][0] + bias[c0c], acc[mf][nf][1] + bias[c0c + 1]);
                *(float2*)&C[(size_t)r_hi * NK + c0c] =
                    make_float2(acc[mf][nf][2] + bias[c0c], acc[mf][nf][3] + bias[c0c + 1]);
            }
        }
    }
}

// ---------------------------------------------------------------------------
// Flash attention, tf32 mma. One block = (b, h, 64-query tile).
// 8 warps (4x2): each warp owns a 16x32 slab of the 64x64 S/O tiles.
// Q fragments hoisted to registers; K/V smem double-buffered with
// register-staged prefetch. S/P staged through a reused smem buffer.
// ---------------------------------------------------------------------------
constexpr int AST = 68;                      // smem row stride (u32)
constexpr int ATILE = 64 * AST;              // u32 per 64x64 tile
constexpr int ATTN_SMEM_BYTES = (5 * ATILE + 3 * 64) * 4;   // K0,K1,V0,V1,Ss + stats

__global__ __launch_bounds__(256)
void attn_tf32(const float* __restrict__ Q, const float* __restrict__ Kp,
               const float* __restrict__ Vp, const int* __restrict__ lengths,
               float* __restrict__ ctx)
{
    extern __shared__ uint32_t smu[];
    uint32_t* Ksb[2] = { smu,              smu + ATILE     };
    uint32_t* Vsb[2] = { smu + 2 * ATILE,  smu + 3 * ATILE };
    uint32_t* Ss     =   smu + 4 * ATILE;   // Q staging, then S/P
    float* rmax  = (float*)(smu + 5 * ATILE);
    float* rsum  = rmax + 64;
    float* rcorr = rsum + 64;

    const int b = blockIdx.z, h = blockIdx.y;
    const int t0 = blockIdx.x * 64;
    const int tid = threadIdx.x;
    const int warp = tid >> 5, lane = tid & 31;
    const int g = lane >> 2, i4 = lane & 3;
    const int mw = warp >> 1;        // 0..3 -> 16-row slab
    const int nw = warp & 1;         // 0..1 -> 32-col slab
    const int m0 = mw * 16;

    const size_t headbase = ((size_t)b * NH + h) * (size_t)NT * ND;
    const float* Qb = Q + headbase + (size_t)t0 * ND;
    const float* Kb = Kp + headbase;
    const float* Vb = Vp + headbase;
    const int len = lengths[b];

    const int lrow = tid >> 2;       // 0..63 (tile load row)
    const int lseg = (tid & 3) * 16; // col base, 16 per thread

    const float* pk = Kb + (size_t)lrow * ND + lseg;
    const float* pv = Vb + (size_t)lrow * ND + lseg;

    float4 rk0, rk1, rk2, rk3, rv0, rv1, rv2, rv3;
    auto prefetch_kv = [&](int kt) {
        size_t off = (size_t)kt * 64 * ND;
        rk0 = *(const float4*)(pk + off);      rk1 = *(const float4*)(pk + off + 4);
        rk2 = *(const float4*)(pk + off + 8);  rk3 = *(const float4*)(pk + off + 12);
        rv0 = *(const float4*)(pv + off);      rv1 = *(const float4*)(pv + off + 4);
        rv2 = *(const float4*)(pv + off + 8);  rv3 = *(const float4*)(pv + off + 12);
    };
    auto store_kv = [&](int buf) {
        uint32_t* dk = &Ksb[buf][lrow * AST + lseg];
        dk[0]=f2tf(rk0.x); dk[1]=f2tf(rk0.y); dk[2]=f2tf(rk0.z); dk[3]=f2tf(rk0.w);
        dk[4]=f2tf(rk1.x); dk[5]=f2tf(rk1.y); dk[6]=f2tf(rk1.z); dk[7]=f2tf(rk1.w);
        dk[8]=f2tf(rk2.x); dk[9]=f2tf(rk2.y); dk[10]=f2tf(rk2.z); dk[11]=f2tf(rk2.w);
        dk[12]=f2tf(rk3.x); dk[13]=f2tf(rk3.y); dk[14]=f2tf(rk3.z); dk[15]=f2tf(rk3.w);
        uint32_t* dv = &Vsb[buf][lrow * AST + lseg];
        dv[0]=f2tf(rv0.x); dv[1]=f2tf(rv0.y); dv[2]=f2tf(rv0.z); dv[3]=f2tf(rv0.w);
        dv[4]=f2tf(rv1.x); dv[5]=f2tf(rv1.y); dv[6]=f2tf(rv1.z); dv[7]=f2tf(rv1.w);
        dv[8]=f2tf(rv2.x); dv[9]=f2tf(rv2.y); dv[10]=f2tf(rv2.z); dv[11]=f2tf(rv2.w);
        dv[12]=f2tf(rv3.x); dv[13]=f2tf(rv3.y); dv[14]=f2tf(rv3.z); dv[15]=f2tf(rv3.w);
    };

    // stage Q into Ss, prefetch K/V tile 0
    #pragma unroll
    for (int s = 0; s < 4; s++) {
        float4 v = *(const float4*)&Qb[lrow * ND + lseg + s * 4];
        uint32_t* d = &Ss[lrow * AST + lseg + s * 4];
        d[0]=f2tf(v.x); d[1]=f2tf(v.y); d[2]=f2tf(v.z); d[3]=f2tf(v.w);
    }
    prefetch_kv(0);
    if (tid < 64) { rmax[tid] = -1e30f; rsum[tid] = 0.0f; }
    __syncthreads();

    // hoist Q fragments to registers (64 K-dim -> 8 frags of 4 regs)
    uint32_t Qf[8][4];
    #pragma unroll
    for (int f = 0; f < 8; f++) {
        int kk = f * 8;
        Qf[f][0] = Ss[(m0 + g    ) * AST + kk + i4];
        Qf[f][1] = Ss[(m0 + g + 8) * AST + kk + i4];
        Qf[f][2] = Ss[(m0 + g    ) * AST + kk + i4 + 4];
        Qf[f][3] = Ss[(m0 + g + 8) * AST + kk + i4 + 4];
    }
    store_kv(0);
    __syncthreads();   // Qf reads done (Ss reusable); K/V tile 0 visible

    float o[4][4] = {};   // [nfrag][4]

    for (int kt = 0; kt < NT / 64; kt++) {
        const int cur = kt & 1;
        if (kt + 1 < NT / 64) prefetch_kv(kt + 1);

        // ---- S = Q . K^T (mma) ----
        const uint32_t* Ks = Ksb[cur];
        float sc[4][4] = {};
        #pragma unroll
        for (int f = 0; f < 8; f++) {
            int kk = f * 8;
            #pragma unroll
            for (int nf = 0; nf < 4; nf++) {
                int nc = nw * 32 + nf * 8;
                uint32_t bf[2] = {
                    Ks[(nc + g) * AST + kk + i4],
                    Ks[(nc + g) * AST + kk + i4 + 4]
                };
                mma_tf32(sc[nf], Qf[f], bf);
            }
        }
        // stage S to smem (float bits)
        #pragma unroll
        for (int nf = 0; nf < 4; nf++) {
            int nc = nw * 32 + nf * 8 + 2 * i4;
            Ss[(m0 + g    ) * AST + nc    ] = __float_as_uint(sc[nf][0]);
            Ss[(m0 + g    ) * AST + nc + 1] = __float_as_uint(sc[nf][1]);
            Ss[(m0 + g + 8) * AST + nc    ] = __float_as_uint(sc[nf][2]);
            Ss[(m0 + g + 8) * AST + nc + 1] = __float_as_uint(sc[nf][3]);
        }
        __syncthreads();

        // ---- online softmax: 4 threads per row ----
        {
            const int row = tid >> 2, part = tid & 3;
            const int cb = part * 16;
            float vals[16];
            float mold = rmax[row];
            float mx = mold;
            #pragma unroll
            for (int c = 0; c < 16; c++) {
                int cg = kt * 64 + cb + c;
                float v = __uint_as_float(Ss[row * AST + cb + c]);
                v += (cg < len) ? 0.0f : -10000.0f;
                vals[c] = v;
                mx = fmaxf(mx, v);
            }
            mx = fmaxf(mx, __shfl_xor_sync(0xffffffffu, mx, 1));
            mx = fmaxf(mx, __shfl_xor_sync(0xffffffffu, mx, 2));
            float sum = 0.0f;
            #pragma unroll
            for (int c = 0; c < 16; c++) {
                float p = __expf(vals[c] - mx);
                sum += p;
                Ss[row * AST + cb + c] = f2tf(p);   // P as tf32 bits
            }
            sum += __shfl_xor_sync(0xffffffffu, sum, 1);
            sum += __shfl_xor_sync(0xffffffffu, sum, 2);
            if (part == 0) {
                float corr = __expf(mold - mx);
                rsum[row] = rsum[row] * corr + sum;
                rmax[row] = mx;
                rcorr[row] = corr;
            }
        }
        __syncthreads();

        // ---- O = O*corr + P . V (mma) ----
        {
            float c_lo = rcorr[m0 + g], c_hi = rcorr[m0 + g + 8];
            #pragma unroll
            for (int nf = 0; nf < 4; nf++) {
                o[nf][0] *= c_lo; o[nf][1] *= c_lo;
                o[nf][2] *= c_hi; o[nf][3] *= c_hi;
            }
        }
        const uint32_t* Vs = Vsb[cur];
        #pragma unroll
        for (int kk = 0; kk < 64; kk += 8) {
            uint32_t af[4] = {
                Ss[(m0 + g    ) * AST + kk + i4],
                Ss[(m0 + g + 8) * AST + kk + i4],
                Ss[(m0 + g    ) * AST + kk + i4 + 4],
                Ss[(m0 + g + 8) * AST + kk + i4 + 4]
            };
            #pragma unroll
            for (int nf = 0; nf < 4; nf++) {
                int nc = nw * 32 + nf * 8;
                uint32_t bf[2] = {
                    Vs[(kk + i4    ) * AST + nc + g],
                    Vs[(kk + i4 + 4) * AST + nc + g]
                };
                mma_tf32(o[nf], af, bf);
            }
        }
        if (kt + 1 < NT / 64) store_kv(cur ^ 1);
        __syncthreads();
    }

    // normalize + write ctx [B*T, K], col = h*64 + n
    {
        float inv_lo = 1.0f / rsum[m0 + g];
        float inv_hi = 1.0f / rsum[m0 + g + 8];
        size_t rb_lo = ((size_t)b * NT + t0 + m0 + g    ) * NK + h * 64;
        size_t rb_hi = ((size_t)b * NT + t0 + m0 + g + 8) * NK + h * 64;
        #pragma unroll
        for (int nf = 0; nf < 4; nf++) {
            int nc = nw * 32 + nf * 8 + 2 * i4;
            *(float2*)&ctx[rb_lo + nc] = make_float2(o[nf][0] * inv_lo, o[nf][1] * inv_lo);
            *(float2*)&ctx[rb_hi + nc] = make_float2(o[nf][2] * inv_hi, o[nf][3] * inv_hi);
        }
    }
}

// ---------------------------------------------------------------------------
extern "C" void kernel_launch(void* const* d_in, const int* in_sizes, int n_in,
                              void* d_out, int out_size)
{
    const float* x0  = (const float*)d_in[0];
    const int* lens  = (const int*)d_in[1];
    const float* Wq  = (const float*)d_in[2];
    const float* Wk  = (const float*)d_in[3];
    const float* Wv  = (const float*)d_in[4];
    const float* Wu  = (const float*)d_in[5];
    const float* bu  = (const float*)d_in[6];
    float* out       = (float*)d_out;

    float* dq;   cudaGetSymbolAddress((void**)&dq,  g_q);
    float* dk;   cudaGetSymbolAddress((void**)&dk,  g_k);
    float* dv;   cudaGetSymbolAddress((void**)&dv,  g_v);
    float* dctx; cudaGetSymbolAddress((void**)&dctx, g_ctx);

    cudaFuncSetAttribute(gemm_tf32, cudaFuncAttributeMaxDynamicSharedMemorySize,
                         GEMM_SMEM_BYTES);
    cudaFuncSetAttribute(attn_tf32, cudaFuncAttributeMaxDynamicSharedMemorySize,
                         ATTN_SMEM_BYTES);

    const float qk_scale = 0.35355339059327373f;  // 64^(-0.25)

    dim3 ggrid(NK / 128, MROWS / 128);   // (8, 64)
    gemm_tf32<<<ggrid, 256, GEMM_SMEM_BYTES>>>(x0, Wq, nullptr, dq, qk_scale, 0);
    gemm_tf32<<<ggrid, 256, GEMM_SMEM_BYTES>>>(x0, Wk, nullptr, dk, qk_scale, 0);
    gemm_tf32<<<ggrid, 256, GEMM_SMEM_BYTES>>>(x0, Wv, nullptr, dv, 1.0f, 0);

    dim3 agrid(NT / 64, NH, NB);         // (32, 16, 4)
    attn_tf32<<<agrid, 256, ATTN_SMEM_BYTES>>>(dq, dk, dv, lens, dctx);

    gemm_tf32<<<ggrid, 256, GEMM_SMEM_BYTES>>>(dctx, Wu, bu, out, 1.0f, 1);
}